// round 7
// baseline (speedup 1.0000x reference)
#include <cuda_runtime.h>
#include <cuda_bf16.h>
#include <cstdint>

// Problem constants
#define BB 4
#define SS 1024
#define DD 1024
#define HH 16
#define HD 64
#define MROWS (BB*SS)          // 4096
#define QSCALE 0.03125f        // 1024^-0.5

// ---------------------------------------------------------------------------
// Scratch
// ---------------------------------------------------------------------------
__device__ __nv_bfloat16 g_xh[(size_t)MROWS * DD],   g_xl[(size_t)MROWS * DD];
__device__ __nv_bfloat16 g_wih[(size_t)DD * 3 * DD], g_wil[(size_t)DD * 3 * DD];
__device__ __nv_bfloat16 g_woh[(size_t)DD * DD],     g_wol[(size_t)DD * DD];
__device__ __nv_bfloat16 g_qh[(size_t)BB*HH*SS*HD],  g_ql[(size_t)BB*HH*SS*HD];
__device__ __nv_bfloat16 g_kh[(size_t)BB*HH*SS*HD],  g_kl[(size_t)BB*HH*SS*HD];
__device__ __nv_bfloat16 g_vh[(size_t)BB*HH*SS*HD],  g_vl[(size_t)BB*HH*SS*HD];
__device__ __nv_bfloat16 g_ph[(size_t)BB*HH*SS*SS],  g_pl[(size_t)BB*HH*SS*SS];
__device__ __nv_bfloat16 g_aoh[(size_t)MROWS * DD],  g_aol[(size_t)MROWS * DD];

// ---------------------------------------------------------------------------
// MMA / ldmatrix / cp.async helpers
// ---------------------------------------------------------------------------
__device__ __forceinline__ void mma16816(float* d, const uint32_t* a, const uint32_t* b) {
    asm volatile(
        "mma.sync.aligned.m16n8k16.row.col.f32.bf16.bf16.f32 "
        "{%0,%1,%2,%3}, {%4,%5,%6,%7}, {%8,%9}, {%0,%1,%2,%3};"
        : "+f"(d[0]), "+f"(d[1]), "+f"(d[2]), "+f"(d[3])
        : "r"(a[0]), "r"(a[1]), "r"(a[2]), "r"(a[3]), "r"(b[0]), "r"(b[1]));
}
__device__ __forceinline__ void ldsm_x4(uint32_t* r, uint32_t addr) {
    asm volatile("ldmatrix.sync.aligned.m8n8.x4.shared.b16 {%0,%1,%2,%3}, [%4];"
                 : "=r"(r[0]), "=r"(r[1]), "=r"(r[2]), "=r"(r[3]) : "r"(addr));
}
__device__ __forceinline__ void ldsm_x2t(uint32_t* r, uint32_t addr) {
    asm volatile("ldmatrix.sync.aligned.m8n8.x2.trans.shared.b16 {%0,%1}, [%2];"
                 : "=r"(r[0]), "=r"(r[1]) : "r"(addr));
}
__device__ __forceinline__ void split_bf16(float v, __nv_bfloat16& h, __nv_bfloat16& l) {
    h = __float2bfloat16(v);
    l = __float2bfloat16(v - __bfloat162float(h));
}
__device__ __forceinline__ void cpa16(uint32_t s, const void* g) {
    asm volatile("cp.async.cg.shared.global [%0], [%1], 16;" :: "r"(s), "l"(g));
}
__device__ __forceinline__ void cp_commit() { asm volatile("cp.async.commit_group;"); }
template<int N> __device__ __forceinline__ void cp_wait() {
    asm volatile("cp.async.wait_group %0;" :: "n"(N));
}

// ---------------------------------------------------------------------------
// split kernel: fp32 -> (hi, lo) bf16
// ---------------------------------------------------------------------------
__global__ __launch_bounds__(256) void split_kernel(
    const float* __restrict__ in, __nv_bfloat16* __restrict__ hi,
    __nv_bfloat16* __restrict__ lo, int n4)
{
    int i = blockIdx.x * 256 + threadIdx.x;
    if (i >= n4) return;
    float4 v = ((const float4*)in)[i];
    __nv_bfloat16 h0, l0, h1, l1, h2, l2, h3, l3;
    split_bf16(v.x, h0, l0); split_bf16(v.y, h1, l1);
    split_bf16(v.z, h2, l2); split_bf16(v.w, h3, l3);
    ((__nv_bfloat162*)hi)[2 * i]     = __nv_bfloat162(h0, h1);
    ((__nv_bfloat162*)hi)[2 * i + 1] = __nv_bfloat162(h2, h3);
    ((__nv_bfloat162*)lo)[2 * i]     = __nv_bfloat162(l0, l1);
    ((__nv_bfloat162*)lo)[2 * i + 1] = __nv_bfloat162(l2, l3);
}

// ---------------------------------------------------------------------------
// GEMM tile constants (BM=BN=128, BK=32, 8 warps = 4m x 2n), 2-stage cp.async
// ---------------------------------------------------------------------------
#define ASTR 40
#define BSTR 136
#define AH_OFF 0
#define AL_OFF 10240
#define BH_OFF 20480
#define BL_OFF 29184
#define STAGE_B 37888
#define GEMM_SMEM (STAGE_B * 2)

// Inner loop: pass-major MMA issue (reuse distance 8) to break HMMA RAW chains
#define GEMM_PROLOG \
    extern __shared__ char dynsm[]; \
    uint32_t smbase = (uint32_t)__cvta_generic_to_shared(dynsm); \
    int bx = blockIdx.x, by = blockIdx.y; \
    int tid = threadIdx.x, lane = tid & 31, wid = tid >> 5; \
    int wm = (wid & 3) * 32, wn = (wid >> 2) * 64; \
    int ar = tid >> 2, ac = (tid & 3) * 8; \
    int br = tid >> 4, bc = (tid & 15) * 8; \
    uint32_t a_off = (uint32_t)((wm + (lane & 15)) * ASTR + (lane >> 4) * 8) * 2; \
    uint32_t b_off = (uint32_t)((lane & 15) * BSTR + wn) * 2; \
    float acc[2][8][4]; \
    _Pragma("unroll") for (int i = 0; i < 2; i++) \
        _Pragma("unroll") for (int j = 0; j < 8; j++) \
            _Pragma("unroll") for (int c = 0; c < 4; c++) acc[i][j][c] = 0.f; \
    const int nk = K >> 5; \
    auto load_stage = [&](int st, int kt) { \
        uint32_t sb = smbase + st * STAGE_B; \
        _Pragma("unroll") for (int i = 0; i < 2; i++) { \
            int row = ar + i * 64; \
            size_t g = (size_t)(by * 128 + row) * K + kt + ac; \
            cpa16(sb + AH_OFF + (uint32_t)(row * ASTR + ac) * 2, Ahg + g); \
            cpa16(sb + AL_OFF + (uint32_t)(row * ASTR + ac) * 2, Alg + g); \
        } \
        _Pragma("unroll") for (int i = 0; i < 2; i++) { \
            int row = br + i * 16; \
            size_t g = (size_t)(kt + row) * N + bx * 128 + bc; \
            cpa16(sb + BH_OFF + (uint32_t)(row * BSTR + bc) * 2, Bhg + g); \
            cpa16(sb + BL_OFF + (uint32_t)(row * BSTR + bc) * 2, Blg + g); \
        } \
        cp_commit(); \
    }; \
    load_stage(0, 0); \
    load_stage(1, 32); \
    for (int i = 0; i < nk; i++) { \
        if (i < nk - 1) cp_wait<1>(); else cp_wait<0>(); \
        __syncthreads(); \
        uint32_t sb = smbase + (i & 1) * STAGE_B; \
        _Pragma("unroll") for (int ks = 0; ks < 2; ks++) { \
            uint32_t ahf[2][4], alf[2][4]; \
            _Pragma("unroll") for (int mi = 0; mi < 2; mi++) { \
                uint32_t off = a_off + (uint32_t)(mi * 16 * ASTR + ks * 16) * 2; \
                ldsm_x4(ahf[mi], sb + AH_OFF + off); \
                ldsm_x4(alf[mi], sb + AL_OFF + off); \
            } \
            _Pragma("unroll") for (int nb = 0; nb < 2; nb++) { \
                uint32_t bhf[4][2], blf[4][2]; \
                _Pragma("unroll") for (int nj = 0; nj < 4; nj++) { \
                    uint32_t off = b_off + (uint32_t)(ks * 16 * BSTR + (nb * 4 + nj) * 8) * 2; \
                    ldsm_x2t(bhf[nj], sb + BH_OFF + off); \
                    ldsm_x2t(blf[nj], sb + BL_OFF + off); \
                } \
                _Pragma("unroll") for (int nj = 0; nj < 4; nj++) \
                    _Pragma("unroll") for (int mi = 0; mi < 2; mi++) \
                        mma16816(acc[mi][nb * 4 + nj], ahf[mi], bhf[nj]); \
                _Pragma("unroll") for (int nj = 0; nj < 4; nj++) \
                    _Pragma("unroll") for (int mi = 0; mi < 2; mi++) \
                        mma16816(acc[mi][nb * 4 + nj], ahf[mi], blf[nj]); \
                _Pragma("unroll") for (int nj = 0; nj < 4; nj++) \
                    _Pragma("unroll") for (int mi = 0; mi < 2; mi++) \
                        mma16816(acc[mi][nb * 4 + nj], alf[mi], bhf[nj]); \
            } \
        } \
        __syncthreads(); \
        if (i + 2 < nk) load_stage((i + 2) & 1, (i + 2) * 32); \
    }

// ---------------------------------------------------------------------------
// QKV GEMM: writes q (scaled), k, v as split bf16 in [b,h,s,d] layout
// ---------------------------------------------------------------------------
__global__ __launch_bounds__(256, 2) void mma_gemm_qkv(
    const __nv_bfloat16* __restrict__ Ahg, const __nv_bfloat16* __restrict__ Alg,
    const __nv_bfloat16* __restrict__ Bhg, const __nv_bfloat16* __restrict__ Blg,
    const float* __restrict__ bias,
    __nv_bfloat16* __restrict__ qh, __nv_bfloat16* __restrict__ ql,
    __nv_bfloat16* __restrict__ kh, __nv_bfloat16* __restrict__ kl,
    __nv_bfloat16* __restrict__ vh, __nv_bfloat16* __restrict__ vl,
    int M, int N, int K)
{
    GEMM_PROLOG

    int part = (bx * 128) >> 10;
    __nv_bfloat16* dh = part == 0 ? qh : (part == 1 ? kh : vh);
    __nv_bfloat16* dl = part == 0 ? ql : (part == 1 ? kl : vl);
    float mul = part == 0 ? QSCALE : 1.0f;
    int head = ((bx * 128 + wn) & 1023) >> 6;
    int bq = (by * 128) >> 10;
    int group = lane >> 2, tig = lane & 3;
    #pragma unroll
    for (int mi = 0; mi < 2; mi++) {
        int s0 = ((by * 128) & 1023) + wm + mi * 16 + group;
        #pragma unroll
        for (int ni = 0; ni < 8; ni++) {
            int col = bx * 128 + wn + ni * 8 + tig * 2;
            int d = ni * 8 + tig * 2;
            float b0 = bias[col], b1 = bias[col + 1];
            float v00 = (acc[mi][ni][0] + b0) * mul, v01 = (acc[mi][ni][1] + b1) * mul;
            float v10 = (acc[mi][ni][2] + b0) * mul, v11 = (acc[mi][ni][3] + b1) * mul;
            size_t o0 = ((size_t)(bq * HH + head) * SS + s0) * HD + d;
            size_t o1 = o0 + 8 * HD;
            __nv_bfloat16 h0, l0, h1, l1;
            split_bf16(v00, h0, l0); split_bf16(v01, h1, l1);
            *(__nv_bfloat162*)&dh[o0] = __nv_bfloat162(h0, h1);
            *(__nv_bfloat162*)&dl[o0] = __nv_bfloat162(l0, l1);
            split_bf16(v10, h0, l0); split_bf16(v11, h1, l1);
            *(__nv_bfloat162*)&dh[o1] = __nv_bfloat162(h0, h1);
            *(__nv_bfloat162*)&dl[o1] = __nv_bfloat162(l0, l1);
        }
    }
}

// ---------------------------------------------------------------------------
// Out-projection GEMM: fp32 output + bias
// ---------------------------------------------------------------------------
__global__ __launch_bounds__(256, 2) void mma_gemm_out(
    const __nv_bfloat16* __restrict__ Ahg, const __nv_bfloat16* __restrict__ Alg,
    const __nv_bfloat16* __restrict__ Bhg, const __nv_bfloat16* __restrict__ Blg,
    const float* __restrict__ bias, float* __restrict__ C,
    int M, int N, int K)
{
    GEMM_PROLOG

    int group = lane >> 2, tig = lane & 3;
    #pragma unroll
    for (int mi = 0; mi < 2; mi++) {
        int row0 = by * 128 + wm + mi * 16 + group;
        #pragma unroll
        for (int ni = 0; ni < 8; ni++) {
            int col = bx * 128 + wn + ni * 8 + tig * 2;
            float b0 = bias[col], b1 = bias[col + 1];
            *(float2*)&C[(size_t)row0 * N + col] =
                make_float2(acc[mi][ni][0] + b0, acc[mi][ni][1] + b1);
            *(float2*)&C[(size_t)(row0 + 8) * N + col] =
                make_float2(acc[mi][ni][2] + b0, acc[mi][ni][3] + b1);
        }
    }
}

// ---------------------------------------------------------------------------
// Scores + softmax (MMA): per (b,h,32q), pass-major MMA issue
// ---------------------------------------------------------------------------
#define SC2_QH 132096
#define SC2_QL 136704
#define SC2_K  141312
#define SC2_KSTAGE 36864
#define SC2_SMEM 215040

__global__ __launch_bounds__(256) void attn_scores_mma(
    const __nv_bfloat16* __restrict__ qh, const __nv_bfloat16* __restrict__ ql,
    const __nv_bfloat16* __restrict__ kh, const __nv_bfloat16* __restrict__ kl,
    __nv_bfloat16* __restrict__ Ph, __nv_bfloat16* __restrict__ Pl)
{
    extern __shared__ char dynsm[];
    float* Ssc = (float*)dynsm;
    uint32_t smbase = (uint32_t)__cvta_generic_to_shared(dynsm);

    int b = blockIdx.z, h = blockIdx.y, q0 = blockIdx.x * 32;
    int tid = threadIdx.x, lane = tid & 31, wid = tid >> 5;
    int wm = (wid & 1) * 16;
    int wn = (wid >> 1) * 32;

    {
        size_t qb = ((size_t)(b * HH + h) * SS + q0) * HD;
        int row = tid >> 3, c8 = (tid & 7) * 8;
        *(uint4*)(dynsm + SC2_QH + (row * 72 + c8) * 2) = *(const uint4*)&qh[qb + row * 64 + c8];
        *(uint4*)(dynsm + SC2_QL + (row * 72 + c8) * 2) = *(const uint4*)&ql[qb + row * 64 + c8];
    }

    auto load_k = [&](int st, int kt) {
        uint32_t kb = smbase + SC2_K + st * SC2_KSTAGE;
        size_t gb = ((size_t)(b * HH + h) * SS + kt) * HD;
        #pragma unroll
        for (int it = 0; it < 4; it++) {
            int idx = tid + it * 256;
            int row = idx >> 3, c8 = (idx & 7) * 8;
            cpa16(kb + (uint32_t)(row * 72 + c8) * 2, kh + gb + row * 64 + c8);
            cpa16(kb + 18432 + (uint32_t)(row * 72 + c8) * 2, kl + gb + row * 64 + c8);
        }
        cp_commit();
    };
    load_k(0, 0);
    load_k(1, 128);

    uint32_t aq_off = (uint32_t)((wm + (lane & 15)) * 72 + (lane >> 4) * 8) * 2;
    int rr_ = lane & 7, halfk = (lane >> 3) & 1, q2 = lane >> 4;
    uint32_t bk_off = (uint32_t)((wn + q2 * 8 + rr_) * 72 + halfk * 8) * 2;

    for (int i = 0; i < 8; i++) {
        if (i < 7) cp_wait<1>(); else cp_wait<0>();
        __syncthreads();
        uint32_t kb = smbase + SC2_K + (i & 1) * SC2_KSTAGE;

        float acc[4][4];
        #pragma unroll
        for (int a = 0; a < 4; a++)
            #pragma unroll
            for (int c = 0; c < 4; c++) acc[a][c] = 0.f;

        #pragma unroll
        for (int ks = 0; ks < 4; ks++) {
            uint32_t ahf[4], alf[4];
            ldsm_x4(ahf, smbase + SC2_QH + aq_off + ks * 32);
            ldsm_x4(alf, smbase + SC2_QL + aq_off + ks * 32);
            uint32_t bhf[2][4], blf[2][4];
            #pragma unroll
            for (int ni2 = 0; ni2 < 2; ni2++) {
                uint32_t boff = bk_off + (uint32_t)(ni2 * 16 * 72 + ks * 16) * 2;
                ldsm_x4(bhf[ni2], kb + boff);
                ldsm_x4(blf[ni2], kb + 18432 + boff);
            }
            // pass 1: ah*bh
            #pragma unroll
            for (int ni2 = 0; ni2 < 2; ni2++) {
                mma16816(acc[ni2*2],   ahf, bhf[ni2]);
                mma16816(acc[ni2*2+1], ahf, bhf[ni2] + 2);
            }
            // pass 2: ah*bl
            #pragma unroll
            for (int ni2 = 0; ni2 < 2; ni2++) {
                mma16816(acc[ni2*2],   ahf, blf[ni2]);
                mma16816(acc[ni2*2+1], ahf, blf[ni2] + 2);
            }
            // pass 3: al*bh
            #pragma unroll
            for (int ni2 = 0; ni2 < 2; ni2++) {
                mma16816(acc[ni2*2],   alf, bhf[ni2]);
                mma16816(acc[ni2*2+1], alf, bhf[ni2] + 2);
            }
        }

        int kt = i * 128;
        int group = lane >> 2, tig = lane & 3;
        #pragma unroll
        for (int ni = 0; ni < 4; ni++) {
            int row = wm + group;
            int col = kt + wn + ni * 8 + tig * 2;
            *(float2*)&Ssc[row * 1032 + col]       = make_float2(acc[ni][0], acc[ni][1]);
            *(float2*)&Ssc[(row + 8) * 1032 + col] = make_float2(acc[ni][2], acc[ni][3]);
        }
        __syncthreads();
        if (i + 2 < 8) load_k((i + 2) & 1, (i + 2) * 128);
    }

    for (int rr = 0; rr < 4; rr++) {
        int row = wid * 4 + rr;
        float2 v2[16];
        float m = -1e30f;
        #pragma unroll
        for (int i2 = 0; i2 < 16; i2++) {
            v2[i2] = *(float2*)&Ssc[row * 1032 + (lane + i2 * 32) * 2];
            m = fmaxf(m, fmaxf(v2[i2].x, v2[i2].y));
        }
        #pragma unroll
        for (int o = 16; o; o >>= 1) m = fmaxf(m, __shfl_xor_sync(0xffffffffu, m, o));
        float s = 0.f;
        #pragma unroll
        for (int i2 = 0; i2 < 16; i2++) {
            v2[i2].x = __expf(v2[i2].x - m);
            v2[i2].y = __expf(v2[i2].y - m);
            s += v2[i2].x + v2[i2].y;
        }
        #pragma unroll
        for (int o = 16; o; o >>= 1) s += __shfl_xor_sync(0xffffffffu, s, o);
        float inv = 1.f / s;
        size_t gb = ((size_t)(b * HH + h) * SS + q0 + row) * SS;
        #pragma unroll
        for (int i2 = 0; i2 < 16; i2++) {
            float p0 = v2[i2].x * inv, p1 = v2[i2].y * inv;
            __nv_bfloat16 h0, l0, h1, l1;
            split_bf16(p0, h0, l0); split_bf16(p1, h1, l1);
            size_t o = gb + (size_t)(lane + i2 * 32) * 2;
            *(__nv_bfloat162*)&Ph[o] = __nv_bfloat162(h0, h1);
            *(__nv_bfloat162*)&Pl[o] = __nv_bfloat162(l0, l1);
        }
    }
}

// ---------------------------------------------------------------------------
// PV (MMA): AO = P @ V per (b,h,128q), pass-major MMA issue
// ---------------------------------------------------------------------------
#define PV_PH 0
#define PV_PL 18432
#define PV_VH 36864
#define PV_VL 46080
#define PV_STAGE 55296
#define PV_SMEM 110592

__global__ __launch_bounds__(256) void attn_pv_mma(
    const __nv_bfloat16* __restrict__ Ph, const __nv_bfloat16* __restrict__ Pl,
    const __nv_bfloat16* __restrict__ vh, const __nv_bfloat16* __restrict__ vl,
    __nv_bfloat16* __restrict__ AOh, __nv_bfloat16* __restrict__ AOl)
{
    extern __shared__ char dynsm[];
    uint32_t smbase = (uint32_t)__cvta_generic_to_shared(dynsm);

    int b = blockIdx.z, h = blockIdx.y, q0 = blockIdx.x * 128;
    int tid = threadIdx.x, lane = tid & 31, wid = tid >> 5;

    auto load_stage = [&](int st, int kt) {
        uint32_t sb = smbase + st * PV_STAGE;
        size_t pb = ((size_t)(b * HH + h) * SS + q0) * SS + kt;
        #pragma unroll
        for (int it = 0; it < 4; it++) {
            int idx = tid + it * 256;
            int row = idx >> 3, c8 = (idx & 7) * 8;
            cpa16(sb + PV_PH + (uint32_t)(row * 72 + c8) * 2, Ph + pb + (size_t)row * SS + c8);
            cpa16(sb + PV_PL + (uint32_t)(row * 72 + c8) * 2, Pl + pb + (size_t)row * SS + c8);
        }
        size_t vb = ((size_t)(b * HH + h) * SS + kt) * HD;
        #pragma unroll
        for (int it = 0; it < 2; it++) {
            int idx = tid + it * 256;
            int row = idx >> 3, c8 = (idx & 7) * 8;
            cpa16(sb + PV_VH + (uint32_t)(row * 72 + c8) * 2, vh + vb + row * 64 + c8);
            cpa16(sb + PV_VL + (uint32_t)(row * 72 + c8) * 2, vl + vb + row * 64 + c8);
        }
        cp_commit();
    };

    float acc[8][4];
    #pragma unroll
    for (int a = 0; a < 8; a++)
        #pragma unroll
        for (int c = 0; c < 4; c++) acc[a][c] = 0.f;

    uint32_t ap_off = (uint32_t)((wid * 16 + (lane & 15)) * 72 + (lane >> 4) * 8) * 2;
    uint32_t bv_off = (uint32_t)((lane & 15) * 72) * 2;

    load_stage(0, 0);
    load_stage(1, 64);

    for (int i = 0; i < 16; i++) {
        if (i < 15) cp_wait<1>(); else cp_wait<0>();
        __syncthreads();
        uint32_t sb = smbase + (i & 1) * PV_STAGE;
        #pragma unroll
        for (int ks = 0; ks < 4; ks++) {
            uint32_t ahf[4], alf[4];
            ldsm_x4(ahf, sb + PV_PH + ap_off + ks * 32);
            ldsm_x4(alf, sb + PV_PL + ap_off + ks * 32);
            #pragma unroll
            for (int nb = 0; nb < 2; nb++) {
                uint32_t bhf[4][2], blf[4][2];
                #pragma unroll
                for (int nj = 0; nj < 4; nj++) {
                    uint32_t off = bv_off + (uint32_t)(ks * 16 * 72 + (nb * 4 + nj) * 8) * 2;
                    ldsm_x2t(bhf[nj], sb + PV_VH + off);
                    ldsm_x2t(blf[nj], sb + PV_VL + off);
                }
                #pragma unroll
                for (int nj = 0; nj < 4; nj++) mma16816(acc[nb*4+nj], ahf, bhf[nj]);
                #pragma unroll
                for (int nj = 0; nj < 4; nj++) mma16816(acc[nb*4+nj], ahf, blf[nj]);
                #pragma unroll
                for (int nj = 0; nj < 4; nj++) mma16816(acc[nb*4+nj], alf, bhf[nj]);
            }
        }
        __syncthreads();
        if (i + 2 < 16) load_stage((i + 2) & 1, (i + 2) * 64);
    }

    int group = lane >> 2, tig = lane & 3;
    #pragma unroll
    for (int ni = 0; ni < 8; ni++) {
        int d = ni * 8 + tig * 2;
        int r0 = q0 + wid * 16 + group;
        size_t o0 = (size_t)(b * SS + r0) * DD + h * HD + d;
        size_t o1 = o0 + (size_t)8 * DD;
        __nv_bfloat16 h0, l0, h1, l1;
        split_bf16(acc[ni][0], h0, l0); split_bf16(acc[ni][1], h1, l1);
        *(__nv_bfloat162*)&AOh[o0] = __nv_bfloat162(h0, h1);
        *(__nv_bfloat162*)&AOl[o0] = __nv_bfloat162(l0, l1);
        split_bf16(acc[ni][2], h0, l0); split_bf16(acc[ni][3], h1, l1);
        *(__nv_bfloat162*)&AOh[o1] = __nv_bfloat162(h0, h1);
        *(__nv_bfloat162*)&AOl[o1] = __nv_bfloat162(l0, l1);
    }
}

// ---------------------------------------------------------------------------
// attn_mean[b,q,k] = (1/H) * sum_h (Ph + Pl)
// ---------------------------------------------------------------------------
__global__ __launch_bounds__(256) void attn_mean_kernel(
    const __nv_bfloat16* __restrict__ Ph, const __nv_bfloat16* __restrict__ Pl,
    float* __restrict__ outm)
{
    size_t g = (size_t)blockIdx.x * 256 + threadIdx.x;
    int k8 = (int)(g & 127);
    size_t t = g >> 7;
    int q = (int)(t & 1023);
    int b = (int)(t >> 10);
    size_t k = (size_t)k8 * 8;

    float acc8[8];
    #pragma unroll
    for (int j = 0; j < 8; j++) acc8[j] = 0.f;
    #pragma unroll
    for (int h = 0; h < HH; h++) {
        size_t off = ((size_t)(b * HH + h) * SS + q) * SS + k;
        uint4 vh4 = *(const uint4*)&Ph[off];
        uint4 vl4 = *(const uint4*)&Pl[off];
        const uint32_t* ph = (const uint32_t*)&vh4;
        const uint32_t* pl = (const uint32_t*)&vl4;
        #pragma unroll
        for (int j = 0; j < 4; j++) {
            __nv_bfloat162 hh = *(__nv_bfloat162*)&ph[j];
            __nv_bfloat162 ll = *(__nv_bfloat162*)&pl[j];
            acc8[2*j]   += __low2float(hh)  + __low2float(ll);
            acc8[2*j+1] += __high2float(hh) + __high2float(ll);
        }
    }
    size_t ob = ((size_t)(b * SS + q)) * SS + k;
    const float inv = 1.0f / HH;
    float4 o0 = make_float4(acc8[0]*inv, acc8[1]*inv, acc8[2]*inv, acc8[3]*inv);
    float4 o1 = make_float4(acc8[4]*inv, acc8[5]*inv, acc8[6]*inv, acc8[7]*inv);
    *(float4*)&outm[ob]     = o0;
    *(float4*)&outm[ob + 4] = o1;
}

// ---------------------------------------------------------------------------
// Host launcher
// ---------------------------------------------------------------------------
extern "C" void kernel_launch(void* const* d_in, const int* in_sizes, int n_in,
                              void* d_out, int out_size)
{
    const float* x     = (const float*)d_in[0];
    const float* w_in  = (const float*)d_in[1];
    const float* b_in  = (const float*)d_in[2];
    const float* w_out = (const float*)d_in[3];
    const float* b_out = (const float*)d_in[4];
    float* out = (float*)d_out;

    __nv_bfloat16 *xh, *xl, *wih, *wil, *woh, *wol;
    __nv_bfloat16 *qh, *ql, *kh, *kl, *vh, *vl, *ph, *pl, *aoh, *aol;
    cudaGetSymbolAddress((void**)&xh,  g_xh);
    cudaGetSymbolAddress((void**)&xl,  g_xl);
    cudaGetSymbolAddress((void**)&wih, g_wih);
    cudaGetSymbolAddress((void**)&wil, g_wil);
    cudaGetSymbolAddress((void**)&woh, g_woh);
    cudaGetSymbolAddress((void**)&wol, g_wol);
    cudaGetSymbolAddress((void**)&qh,  g_qh);
    cudaGetSymbolAddress((void**)&ql,  g_ql);
    cudaGetSymbolAddress((void**)&kh,  g_kh);
    cudaGetSymbolAddress((void**)&kl,  g_kl);
    cudaGetSymbolAddress((void**)&vh,  g_vh);
    cudaGetSymbolAddress((void**)&vl,  g_vl);
    cudaGetSymbolAddress((void**)&ph,  g_ph);
    cudaGetSymbolAddress((void**)&pl,  g_pl);
    cudaGetSymbolAddress((void**)&aoh, g_aoh);
    cudaGetSymbolAddress((void**)&aol, g_aol);

    cudaFuncSetAttribute(mma_gemm_qkv,
                         cudaFuncAttributeMaxDynamicSharedMemorySize, GEMM_SMEM);
    cudaFuncSetAttribute(mma_gemm_out,
                         cudaFuncAttributeMaxDynamicSharedMemorySize, GEMM_SMEM);
    cudaFuncSetAttribute(attn_scores_mma,
                         cudaFuncAttributeMaxDynamicSharedMemorySize, SC2_SMEM);
    cudaFuncSetAttribute(attn_pv_mma,
                         cudaFuncAttributeMaxDynamicSharedMemorySize, PV_SMEM);

    // 0. pre-split inputs
    split_kernel<<<(MROWS * DD / 4 + 255) / 256, 256>>>(x, xh, xl, MROWS * DD / 4);
    split_kernel<<<(DD * 3 * DD / 4 + 255) / 256, 256>>>(w_in, wih, wil, DD * 3 * DD / 4);
    split_kernel<<<(DD * DD / 4 + 255) / 256, 256>>>(w_out, woh, wol, DD * DD / 4);

    // 1. QKV GEMM -> split q/k/v per head
    mma_gemm_qkv<<<dim3(3 * DD / 128, MROWS / 128), 256, GEMM_SMEM>>>(
        xh, xl, wih, wil, b_in, qh, ql, kh, kl, vh, vl, MROWS, 3 * DD, DD);

    // 2. scores + softmax (MMA) -> split P
    attn_scores_mma<<<dim3(SS / 32, HH, BB), 256, SC2_SMEM>>>(qh, ql, kh, kl, ph, pl);

    // 3. P @ V (MMA) -> split AO
    attn_pv_mma<<<dim3(SS / 128, HH, BB), 256, PV_SMEM>>>(ph, pl, vh, vl, aoh, aol);

    // 4. head-mean
    attn_mean_kernel<<<(BB * SS * SS / 8) / 256, 256>>>(ph, pl, out + (size_t)BB * SS * SS);

    // 5. output projection
    mma_gemm_out<<<dim3(DD / 128, MROWS / 128), 256, GEMM_SMEM>>>(
        aoh, aol, woh, wol, b_out, out, MROWS, DD, DD);
}

// round 8
// speedup vs baseline: 1.1632x; 1.1632x over previous
#include <cuda_runtime.h>
#include <cuda_bf16.h>
#include <cstdint>

// Problem constants
#define BB 4
#define SS 1024
#define DD 1024
#define HH 16
#define HD 64
#define MROWS (BB*SS)          // 4096
#define QSCALE 0.03125f        // 1024^-0.5

// ---------------------------------------------------------------------------
// Scratch
// ---------------------------------------------------------------------------
__device__ __nv_bfloat16 g_xh[(size_t)MROWS * DD],   g_xl[(size_t)MROWS * DD];
__device__ __nv_bfloat16 g_wih[(size_t)DD * 3 * DD], g_wil[(size_t)DD * 3 * DD];
__device__ __nv_bfloat16 g_woh[(size_t)DD * DD],     g_wol[(size_t)DD * DD];
__device__ __nv_bfloat16 g_qh[(size_t)BB*HH*SS*HD],  g_ql[(size_t)BB*HH*SS*HD];
__device__ __nv_bfloat16 g_kh[(size_t)BB*HH*SS*HD],  g_kl[(size_t)BB*HH*SS*HD];
__device__ __nv_bfloat16 g_vh[(size_t)BB*HH*SS*HD],  g_vl[(size_t)BB*HH*SS*HD];
__device__ __nv_bfloat16 g_ph[(size_t)BB*HH*SS*SS],  g_pl[(size_t)BB*HH*SS*SS];
__device__ __nv_bfloat16 g_aoh[(size_t)MROWS * DD],  g_aol[(size_t)MROWS * DD];

// ---------------------------------------------------------------------------
// MMA / ldmatrix / cp.async helpers
// ---------------------------------------------------------------------------
__device__ __forceinline__ void mma16816(float* d, const uint32_t* a, const uint32_t* b) {
    asm volatile(
        "mma.sync.aligned.m16n8k16.row.col.f32.bf16.bf16.f32 "
        "{%0,%1,%2,%3}, {%4,%5,%6,%7}, {%8,%9}, {%0,%1,%2,%3};"
        : "+f"(d[0]), "+f"(d[1]), "+f"(d[2]), "+f"(d[3])
        : "r"(a[0]), "r"(a[1]), "r"(a[2]), "r"(a[3]), "r"(b[0]), "r"(b[1]));
}
__device__ __forceinline__ void ldsm_x4(uint32_t* r, uint32_t addr) {
    asm volatile("ldmatrix.sync.aligned.m8n8.x4.shared.b16 {%0,%1,%2,%3}, [%4];"
                 : "=r"(r[0]), "=r"(r[1]), "=r"(r[2]), "=r"(r[3]) : "r"(addr));
}
__device__ __forceinline__ void ldsm_x2t(uint32_t* r, uint32_t addr) {
    asm volatile("ldmatrix.sync.aligned.m8n8.x2.trans.shared.b16 {%0,%1}, [%2];"
                 : "=r"(r[0]), "=r"(r[1]) : "r"(addr));
}
__device__ __forceinline__ void split_bf16(float v, __nv_bfloat16& h, __nv_bfloat16& l) {
    h = __float2bfloat16(v);
    l = __float2bfloat16(v - __bfloat162float(h));
}
__device__ __forceinline__ void cpa16(uint32_t s, const void* g) {
    asm volatile("cp.async.cg.shared.global [%0], [%1], 16;" :: "r"(s), "l"(g));
}
__device__ __forceinline__ void cp_commit() { asm volatile("cp.async.commit_group;"); }
template<int N> __device__ __forceinline__ void cp_wait() {
    asm volatile("cp.async.wait_group %0;" :: "n"(N));
}

// ---------------------------------------------------------------------------
// split kernel: fp32 -> (hi, lo) bf16
// ---------------------------------------------------------------------------
__global__ __launch_bounds__(256) void split_kernel(
    const float* __restrict__ in, __nv_bfloat16* __restrict__ hi,
    __nv_bfloat16* __restrict__ lo, int n4)
{
    int i = blockIdx.x * 256 + threadIdx.x;
    if (i >= n4) return;
    float4 v = ((const float4*)in)[i];
    __nv_bfloat16 h0, l0, h1, l1, h2, l2, h3, l3;
    split_bf16(v.x, h0, l0); split_bf16(v.y, h1, l1);
    split_bf16(v.z, h2, l2); split_bf16(v.w, h3, l3);
    ((__nv_bfloat162*)hi)[2 * i]     = __nv_bfloat162(h0, h1);
    ((__nv_bfloat162*)hi)[2 * i + 1] = __nv_bfloat162(h2, h3);
    ((__nv_bfloat162*)lo)[2 * i]     = __nv_bfloat162(l0, l1);
    ((__nv_bfloat162*)lo)[2 * i + 1] = __nv_bfloat162(l2, l3);
}

// ---------------------------------------------------------------------------
// GEMM tile constants (BM=BN=128, BK=32, 8 warps = 4m x 2n)
// 3-stage cp.async pipeline, ONE barrier per iter.
// p3expr (per-CTA uniform): 3-pass (load+use B-lo) vs 2-pass (B-hi only).
// ---------------------------------------------------------------------------
#define ASTR 40
#define BSTR 136
#define AH_OFF 0
#define AL_OFF 10240
#define BH_OFF 20480
#define BL_OFF 29184
#define STAGE_B 37888
#define GEMM_SMEM (STAGE_B * 3)

#define GEMM_PROLOG(p3expr) \
    extern __shared__ char dynsm[]; \
    uint32_t smbase = (uint32_t)__cvta_generic_to_shared(dynsm); \
    int bx = blockIdx.x, by = blockIdx.y; \
    int tid = threadIdx.x, lane = tid & 31, wid = tid >> 5; \
    int wm = (wid & 3) * 32, wn = (wid >> 2) * 64; \
    int ar = tid >> 2, ac = (tid & 3) * 8; \
    int br = tid >> 4, bc = (tid & 15) * 8; \
    const bool p3 = (p3expr); \
    uint32_t a_off = (uint32_t)((wm + (lane & 15)) * ASTR + (lane >> 4) * 8) * 2; \
    uint32_t b_off = (uint32_t)((lane & 15) * BSTR + wn) * 2; \
    float acc[2][8][4]; \
    _Pragma("unroll") for (int i = 0; i < 2; i++) \
        _Pragma("unroll") for (int j = 0; j < 8; j++) \
            _Pragma("unroll") for (int c = 0; c < 4; c++) acc[i][j][c] = 0.f; \
    const int nk = K >> 5; \
    auto load_stage = [&](int st, int kt) { \
        uint32_t sb = smbase + st * STAGE_B; \
        _Pragma("unroll") for (int i = 0; i < 2; i++) { \
            int row = ar + i * 64; \
            size_t g = (size_t)(by * 128 + row) * K + kt + ac; \
            cpa16(sb + AH_OFF + (uint32_t)(row * ASTR + ac) * 2, Ahg + g); \
            cpa16(sb + AL_OFF + (uint32_t)(row * ASTR + ac) * 2, Alg + g); \
        } \
        _Pragma("unroll") for (int i = 0; i < 2; i++) { \
            int row = br + i * 16; \
            size_t g = (size_t)(kt + row) * N + bx * 128 + bc; \
            cpa16(sb + BH_OFF + (uint32_t)(row * BSTR + bc) * 2, Bhg + g); \
            if (p3) cpa16(sb + BL_OFF + (uint32_t)(row * BSTR + bc) * 2, Blg + g); \
        } \
        cp_commit(); \
    }; \
    load_stage(0, 0); \
    load_stage(1, 32); \
    for (int i = 0; i < nk; i++) { \
        if (i + 1 < nk) cp_wait<1>(); else cp_wait<0>(); \
        __syncthreads(); \
        if (i + 2 < nk) load_stage((i + 2) % 3, (i + 2) * 32); \
        uint32_t sb = smbase + (i % 3) * STAGE_B; \
        _Pragma("unroll") for (int ks = 0; ks < 2; ks++) { \
            uint32_t ahf[2][4], alf[2][4]; \
            _Pragma("unroll") for (int mi = 0; mi < 2; mi++) { \
                uint32_t off = a_off + (uint32_t)(mi * 16 * ASTR + ks * 16) * 2; \
                ldsm_x4(ahf[mi], sb + AH_OFF + off); \
                ldsm_x4(alf[mi], sb + AL_OFF + off); \
            } \
            _Pragma("unroll") for (int nb = 0; nb < 2; nb++) { \
                uint32_t bhf[4][2]; \
                _Pragma("unroll") for (int nj = 0; nj < 4; nj++) { \
                    uint32_t off = b_off + (uint32_t)(ks * 16 * BSTR + (nb * 4 + nj) * 8) * 2; \
                    ldsm_x2t(bhf[nj], sb + BH_OFF + off); \
                } \
                _Pragma("unroll") for (int nj = 0; nj < 4; nj++) \
                    _Pragma("unroll") for (int mi = 0; mi < 2; mi++) \
                        mma16816(acc[mi][nb * 4 + nj], ahf[mi], bhf[nj]); \
                _Pragma("unroll") for (int nj = 0; nj < 4; nj++) \
                    _Pragma("unroll") for (int mi = 0; mi < 2; mi++) \
                        mma16816(acc[mi][nb * 4 + nj], alf[mi], bhf[nj]); \
                if (p3) { \
                    uint32_t blf[4][2]; \
                    _Pragma("unroll") for (int nj = 0; nj < 4; nj++) { \
                        uint32_t off = b_off + (uint32_t)(ks * 16 * BSTR + (nb * 4 + nj) * 8) * 2; \
                        ldsm_x2t(blf[nj], sb + BL_OFF + off); \
                    } \
                    _Pragma("unroll") for (int nj = 0; nj < 4; nj++) \
                        _Pragma("unroll") for (int mi = 0; mi < 2; mi++) \
                            mma16816(acc[mi][nb * 4 + nj], ahf[mi], blf[nj]); \
                } \
            } \
        } \
    } \
    __syncthreads();

// ---------------------------------------------------------------------------
// QKV GEMM: writes q (scaled), k, v as split bf16 in [b,h,s,d] layout
// q,k thirds: 2-pass (B-lo dropped); v third: 3-pass (feeds output directly)
// ---------------------------------------------------------------------------
__global__ __launch_bounds__(256, 2) void mma_gemm_qkv(
    const __nv_bfloat16* __restrict__ Ahg, const __nv_bfloat16* __restrict__ Alg,
    const __nv_bfloat16* __restrict__ Bhg, const __nv_bfloat16* __restrict__ Blg,
    const float* __restrict__ bias,
    __nv_bfloat16* __restrict__ qh, __nv_bfloat16* __restrict__ ql,
    __nv_bfloat16* __restrict__ kh, __nv_bfloat16* __restrict__ kl,
    __nv_bfloat16* __restrict__ vh, __nv_bfloat16* __restrict__ vl,
    int M, int N, int K)
{
    GEMM_PROLOG(blockIdx.x >= 16)   // v part (cols >= 2048) gets 3 passes

    int part = (bx * 128) >> 10;
    __nv_bfloat16* dh = part == 0 ? qh : (part == 1 ? kh : vh);
    __nv_bfloat16* dl = part == 0 ? ql : (part == 1 ? kl : vl);
    float mul = part == 0 ? QSCALE : 1.0f;
    int head = ((bx * 128 + wn) & 1023) >> 6;
    int bq = (by * 128) >> 10;
    int group = lane >> 2, tig = lane & 3;
    #pragma unroll
    for (int mi = 0; mi < 2; mi++) {
        int s0 = ((by * 128) & 1023) + wm + mi * 16 + group;
        #pragma unroll
        for (int ni = 0; ni < 8; ni++) {
            int col = bx * 128 + wn + ni * 8 + tig * 2;
            int d = ni * 8 + tig * 2;
            float b0 = bias[col], b1 = bias[col + 1];
            float v00 = (acc[mi][ni][0] + b0) * mul, v01 = (acc[mi][ni][1] + b1) * mul;
            float v10 = (acc[mi][ni][2] + b0) * mul, v11 = (acc[mi][ni][3] + b1) * mul;
            size_t o0 = ((size_t)(bq * HH + head) * SS + s0) * HD + d;
            size_t o1 = o0 + 8 * HD;
            __nv_bfloat16 h0, l0, h1, l1;
            split_bf16(v00, h0, l0); split_bf16(v01, h1, l1);
            *(__nv_bfloat162*)&dh[o0] = __nv_bfloat162(h0, h1);
            *(__nv_bfloat162*)&dl[o0] = __nv_bfloat162(l0, l1);
            split_bf16(v10, h0, l0); split_bf16(v11, h1, l1);
            *(__nv_bfloat162*)&dh[o1] = __nv_bfloat162(h0, h1);
            *(__nv_bfloat162*)&dl[o1] = __nv_bfloat162(l0, l1);
        }
    }
}

// ---------------------------------------------------------------------------
// Out-projection GEMM: fp32 output + bias, full 3-pass
// ---------------------------------------------------------------------------
__global__ __launch_bounds__(256, 2) void mma_gemm_out(
    const __nv_bfloat16* __restrict__ Ahg, const __nv_bfloat16* __restrict__ Alg,
    const __nv_bfloat16* __restrict__ Bhg, const __nv_bfloat16* __restrict__ Blg,
    const float* __restrict__ bias, float* __restrict__ C,
    int M, int N, int K)
{
    GEMM_PROLOG(true)

    int group = lane >> 2, tig = lane & 3;
    #pragma unroll
    for (int mi = 0; mi < 2; mi++) {
        int row0 = by * 128 + wm + mi * 16 + group;
        #pragma unroll
        for (int ni = 0; ni < 8; ni++) {
            int col = bx * 128 + wn + ni * 8 + tig * 2;
            float b0 = bias[col], b1 = bias[col + 1];
            *(float2*)&C[(size_t)row0 * N + col] =
                make_float2(acc[mi][ni][0] + b0, acc[mi][ni][1] + b1);
            *(float2*)&C[(size_t)(row0 + 8) * N + col] =
                make_float2(acc[mi][ni][2] + b0, acc[mi][ni][3] + b1);
        }
    }
}

// ---------------------------------------------------------------------------
// Scores + softmax (MMA): per (b,h,32q). 2-pass: S = qh*kh + ql*kh.
// K-lo never loaded. smem: Ssc fp32[32][1032] | Qh/Ql [32][72] | Kh x2 stages
// ---------------------------------------------------------------------------
#define SC2_QH 132096
#define SC2_QL 136704
#define SC2_K  141312
#define SC2_KSTAGE 18432
#define SC2_SMEM 178176

__global__ __launch_bounds__(256) void attn_scores_mma(
    const __nv_bfloat16* __restrict__ qh, const __nv_bfloat16* __restrict__ ql,
    const __nv_bfloat16* __restrict__ kh,
    __nv_bfloat16* __restrict__ Ph, __nv_bfloat16* __restrict__ Pl)
{
    extern __shared__ char dynsm[];
    float* Ssc = (float*)dynsm;
    uint32_t smbase = (uint32_t)__cvta_generic_to_shared(dynsm);

    int b = blockIdx.z, h = blockIdx.y, q0 = blockIdx.x * 32;
    int tid = threadIdx.x, lane = tid & 31, wid = tid >> 5;
    int wm = (wid & 1) * 16;
    int wn = (wid >> 1) * 32;

    {
        size_t qb = ((size_t)(b * HH + h) * SS + q0) * HD;
        int row = tid >> 3, c8 = (tid & 7) * 8;
        *(uint4*)(dynsm + SC2_QH + (row * 72 + c8) * 2) = *(const uint4*)&qh[qb + row * 64 + c8];
        *(uint4*)(dynsm + SC2_QL + (row * 72 + c8) * 2) = *(const uint4*)&ql[qb + row * 64 + c8];
    }

    auto load_k = [&](int st, int kt) {
        uint32_t kb = smbase + SC2_K + st * SC2_KSTAGE;
        size_t gb = ((size_t)(b * HH + h) * SS + kt) * HD;
        #pragma unroll
        for (int it = 0; it < 4; it++) {
            int idx = tid + it * 256;
            int row = idx >> 3, c8 = (idx & 7) * 8;
            cpa16(kb + (uint32_t)(row * 72 + c8) * 2, kh + gb + row * 64 + c8);
        }
        cp_commit();
    };
    load_k(0, 0);
    load_k(1, 128);

    uint32_t aq_off = (uint32_t)((wm + (lane & 15)) * 72 + (lane >> 4) * 8) * 2;
    int rr_ = lane & 7, halfk = (lane >> 3) & 1, q2 = lane >> 4;
    uint32_t bk_off = (uint32_t)((wn + q2 * 8 + rr_) * 72 + halfk * 8) * 2;

    for (int i = 0; i < 8; i++) {
        if (i < 7) cp_wait<1>(); else cp_wait<0>();
        __syncthreads();
        uint32_t kb = smbase + SC2_K + (i & 1) * SC2_KSTAGE;

        float acc[4][4];
        #pragma unroll
        for (int a = 0; a < 4; a++)
            #pragma unroll
            for (int c = 0; c < 4; c++) acc[a][c] = 0.f;

        #pragma unroll
        for (int ks = 0; ks < 4; ks++) {
            uint32_t ahf[4], alf[4];
            ldsm_x4(ahf, smbase + SC2_QH + aq_off + ks * 32);
            ldsm_x4(alf, smbase + SC2_QL + aq_off + ks * 32);
            uint32_t bhf[2][4];
            #pragma unroll
            for (int ni2 = 0; ni2 < 2; ni2++) {
                uint32_t boff = bk_off + (uint32_t)(ni2 * 16 * 72 + ks * 16) * 2;
                ldsm_x4(bhf[ni2], kb + boff);
            }
            // pass 1: qh*kh
            #pragma unroll
            for (int ni2 = 0; ni2 < 2; ni2++) {
                mma16816(acc[ni2*2],   ahf, bhf[ni2]);
                mma16816(acc[ni2*2+1], ahf, bhf[ni2] + 2);
            }
            // pass 2: ql*kh
            #pragma unroll
            for (int ni2 = 0; ni2 < 2; ni2++) {
                mma16816(acc[ni2*2],   alf, bhf[ni2]);
                mma16816(acc[ni2*2+1], alf, bhf[ni2] + 2);
            }
        }

        int kt = i * 128;
        int group = lane >> 2, tig = lane & 3;
        #pragma unroll
        for (int ni = 0; ni < 4; ni++) {
            int row = wm + group;
            int col = kt + wn + ni * 8 + tig * 2;
            *(float2*)&Ssc[row * 1032 + col]       = make_float2(acc[ni][0], acc[ni][1]);
            *(float2*)&Ssc[(row + 8) * 1032 + col] = make_float2(acc[ni][2], acc[ni][3]);
        }
        __syncthreads();
        if (i + 2 < 8) load_k((i + 2) & 1, (i + 2) * 128);
    }

    for (int rr = 0; rr < 4; rr++) {
        int row = wid * 4 + rr;
        float2 v2[16];
        float m = -1e30f;
        #pragma unroll
        for (int i2 = 0; i2 < 16; i2++) {
            v2[i2] = *(float2*)&Ssc[row * 1032 + (lane + i2 * 32) * 2];
            m = fmaxf(m, fmaxf(v2[i2].x, v2[i2].y));
        }
        #pragma unroll
        for (int o = 16; o; o >>= 1) m = fmaxf(m, __shfl_xor_sync(0xffffffffu, m, o));
        float s = 0.f;
        #pragma unroll
        for (int i2 = 0; i2 < 16; i2++) {
            v2[i2].x = __expf(v2[i2].x - m);
            v2[i2].y = __expf(v2[i2].y - m);
            s += v2[i2].x + v2[i2].y;
        }
        #pragma unroll
        for (int o = 16; o; o >>= 1) s += __shfl_xor_sync(0xffffffffu, s, o);
        float inv = 1.f / s;
        size_t gb = ((size_t)(b * HH + h) * SS + q0 + row) * SS;
        #pragma unroll
        for (int i2 = 0; i2 < 16; i2++) {
            float p0 = v2[i2].x * inv, p1 = v2[i2].y * inv;
            __nv_bfloat16 h0, l0, h1, l1;
            split_bf16(p0, h0, l0); split_bf16(p1, h1, l1);
            size_t o = gb + (size_t)(lane + i2 * 32) * 2;
            *(__nv_bfloat162*)&Ph[o] = __nv_bfloat162(h0, h1);
            *(__nv_bfloat162*)&Pl[o] = __nv_bfloat162(l0, l1);
        }
    }
}

// ---------------------------------------------------------------------------
// PV (MMA): AO = P @ V per (b,h,128q), full 3-pass (accuracy-critical)
// ---------------------------------------------------------------------------
#define PV_PH 0
#define PV_PL 18432
#define PV_VH 36864
#define PV_VL 46080
#define PV_STAGE 55296
#define PV_SMEM 110592

__global__ __launch_bounds__(256) void attn_pv_mma(
    const __nv_bfloat16* __restrict__ Ph, const __nv_bfloat16* __restrict__ Pl,
    const __nv_bfloat16* __restrict__ vh, const __nv_bfloat16* __restrict__ vl,
    __nv_bfloat16* __restrict__ AOh, __nv_bfloat16* __restrict__ AOl)
{
    extern __shared__ char dynsm[];
    uint32_t smbase = (uint32_t)__cvta_generic_to_shared(dynsm);

    int b = blockIdx.z, h = blockIdx.y, q0 = blockIdx.x * 128;
    int tid = threadIdx.x, lane = tid & 31, wid = tid >> 5;

    auto load_stage = [&](int st, int kt) {
        uint32_t sb = smbase + st * PV_STAGE;
        size_t pb = ((size_t)(b * HH + h) * SS + q0) * SS + kt;
        #pragma unroll
        for (int it = 0; it < 4; it++) {
            int idx = tid + it * 256;
            int row = idx >> 3, c8 = (idx & 7) * 8;
            cpa16(sb + PV_PH + (uint32_t)(row * 72 + c8) * 2, Ph + pb + (size_t)row * SS + c8);
            cpa16(sb + PV_PL + (uint32_t)(row * 72 + c8) * 2, Pl + pb + (size_t)row * SS + c8);
        }
        size_t vb = ((size_t)(b * HH + h) * SS + kt) * HD;
        #pragma unroll
        for (int it = 0; it < 2; it++) {
            int idx = tid + it * 256;
            int row = idx >> 3, c8 = (idx & 7) * 8;
            cpa16(sb + PV_VH + (uint32_t)(row * 72 + c8) * 2, vh + vb + row * 64 + c8);
            cpa16(sb + PV_VL + (uint32_t)(row * 72 + c8) * 2, vl + vb + row * 64 + c8);
        }
        cp_commit();
    };

    float acc[8][4];
    #pragma unroll
    for (int a = 0; a < 8; a++)
        #pragma unroll
        for (int c = 0; c < 4; c++) acc[a][c] = 0.f;

    uint32_t ap_off = (uint32_t)((wid * 16 + (lane & 15)) * 72 + (lane >> 4) * 8) * 2;
    uint32_t bv_off = (uint32_t)((lane & 15) * 72) * 2;

    load_stage(0, 0);
    load_stage(1, 64);

    for (int i = 0; i < 16; i++) {
        if (i < 15) cp_wait<1>(); else cp_wait<0>();
        __syncthreads();
        uint32_t sb = smbase + (i & 1) * PV_STAGE;
        #pragma unroll
        for (int ks = 0; ks < 4; ks++) {
            uint32_t ahf[4], alf[4];
            ldsm_x4(ahf, sb + PV_PH + ap_off + ks * 32);
            ldsm_x4(alf, sb + PV_PL + ap_off + ks * 32);
            #pragma unroll
            for (int nb = 0; nb < 2; nb++) {
                uint32_t bhf[4][2], blf[4][2];
                #pragma unroll
                for (int nj = 0; nj < 4; nj++) {
                    uint32_t off = bv_off + (uint32_t)(ks * 16 * 72 + (nb * 4 + nj) * 8) * 2;
                    ldsm_x2t(bhf[nj], sb + PV_VH + off);
                    ldsm_x2t(blf[nj], sb + PV_VL + off);
                }
                #pragma unroll
                for (int nj = 0; nj < 4; nj++) mma16816(acc[nb*4+nj], ahf, bhf[nj]);
                #pragma unroll
                for (int nj = 0; nj < 4; nj++) mma16816(acc[nb*4+nj], ahf, blf[nj]);
                #pragma unroll
                for (int nj = 0; nj < 4; nj++) mma16816(acc[nb*4+nj], alf, bhf[nj]);
            }
        }
        __syncthreads();
        if (i + 2 < 16) load_stage((i + 2) & 1, (i + 2) * 64);
    }

    int group = lane >> 2, tig = lane & 3;
    #pragma unroll
    for (int ni = 0; ni < 8; ni++) {
        int d = ni * 8 + tig * 2;
        int r0 = q0 + wid * 16 + group;
        size_t o0 = (size_t)(b * SS + r0) * DD + h * HD + d;
        size_t o1 = o0 + (size_t)8 * DD;
        __nv_bfloat16 h0, l0, h1, l1;
        split_bf16(acc[ni][0], h0, l0); split_bf16(acc[ni][1], h1, l1);
        *(__nv_bfloat162*)&AOh[o0] = __nv_bfloat162(h0, h1);
        *(__nv_bfloat162*)&AOl[o0] = __nv_bfloat162(l0, l1);
        split_bf16(acc[ni][2], h0, l0); split_bf16(acc[ni][3], h1, l1);
        *(__nv_bfloat162*)&AOh[o1] = __nv_bfloat162(h0, h1);
        *(__nv_bfloat162*)&AOl[o1] = __nv_bfloat162(l0, l1);
    }
}

// ---------------------------------------------------------------------------
// attn_mean[b,q,k] = (1/H) * sum_h (Ph + Pl)
// ---------------------------------------------------------------------------
__global__ __launch_bounds__(256) void attn_mean_kernel(
    const __nv_bfloat16* __restrict__ Ph, const __nv_bfloat16* __restrict__ Pl,
    float* __restrict__ outm)
{
    size_t g = (size_t)blockIdx.x * 256 + threadIdx.x;
    int k8 = (int)(g & 127);
    size_t t = g >> 7;
    int q = (int)(t & 1023);
    int b = (int)(t >> 10);
    size_t k = (size_t)k8 * 8;

    float acc8[8];
    #pragma unroll
    for (int j = 0; j < 8; j++) acc8[j] = 0.f;
    #pragma unroll
    for (int h = 0; h < HH; h++) {
        size_t off = ((size_t)(b * HH + h) * SS + q) * SS + k;
        uint4 vh4 = *(const uint4*)&Ph[off];
        uint4 vl4 = *(const uint4*)&Pl[off];
        const uint32_t* ph = (const uint32_t*)&vh4;
        const uint32_t* pl = (const uint32_t*)&vl4;
        #pragma unroll
        for (int j = 0; j < 4; j++) {
            __nv_bfloat162 hh = *(__nv_bfloat162*)&ph[j];
            __nv_bfloat162 ll = *(__nv_bfloat162*)&pl[j];
            acc8[2*j]   += __low2float(hh)  + __low2float(ll);
            acc8[2*j+1] += __high2float(hh) + __high2float(ll);
        }
    }
    size_t ob = ((size_t)(b * SS + q)) * SS + k;
    const float inv = 1.0f / HH;
    float4 o0 = make_float4(acc8[0]*inv, acc8[1]*inv, acc8[2]*inv, acc8[3]*inv);
    float4 o1 = make_float4(acc8[4]*inv, acc8[5]*inv, acc8[6]*inv, acc8[7]*inv);
    *(float4*)&outm[ob]     = o0;
    *(float4*)&outm[ob + 4] = o1;
}

// ---------------------------------------------------------------------------
// Host launcher
// ---------------------------------------------------------------------------
extern "C" void kernel_launch(void* const* d_in, const int* in_sizes, int n_in,
                              void* d_out, int out_size)
{
    const float* x     = (const float*)d_in[0];
    const float* w_in  = (const float*)d_in[1];
    const float* b_in  = (const float*)d_in[2];
    const float* w_out = (const float*)d_in[3];
    const float* b_out = (const float*)d_in[4];
    float* out = (float*)d_out;

    __nv_bfloat16 *xh, *xl, *wih, *wil, *woh, *wol;
    __nv_bfloat16 *qh, *ql, *kh, *kl, *vh, *vl, *ph, *pl, *aoh, *aol;
    cudaGetSymbolAddress((void**)&xh,  g_xh);
    cudaGetSymbolAddress((void**)&xl,  g_xl);
    cudaGetSymbolAddress((void**)&wih, g_wih);
    cudaGetSymbolAddress((void**)&wil, g_wil);
    cudaGetSymbolAddress((void**)&woh, g_woh);
    cudaGetSymbolAddress((void**)&wol, g_wol);
    cudaGetSymbolAddress((void**)&qh,  g_qh);
    cudaGetSymbolAddress((void**)&ql,  g_ql);
    cudaGetSymbolAddress((void**)&kh,  g_kh);
    cudaGetSymbolAddress((void**)&kl,  g_kl);
    cudaGetSymbolAddress((void**)&vh,  g_vh);
    cudaGetSymbolAddress((void**)&vl,  g_vl);
    cudaGetSymbolAddress((void**)&ph,  g_ph);
    cudaGetSymbolAddress((void**)&pl,  g_pl);
    cudaGetSymbolAddress((void**)&aoh, g_aoh);
    cudaGetSymbolAddress((void**)&aol, g_aol);

    cudaFuncSetAttribute(mma_gemm_qkv,
                         cudaFuncAttributeMaxDynamicSharedMemorySize, GEMM_SMEM);
    cudaFuncSetAttribute(mma_gemm_out,
                         cudaFuncAttributeMaxDynamicSharedMemorySize, GEMM_SMEM);
    cudaFuncSetAttribute(attn_scores_mma,
                         cudaFuncAttributeMaxDynamicSharedMemorySize, SC2_SMEM);
    cudaFuncSetAttribute(attn_pv_mma,
                         cudaFuncAttributeMaxDynamicSharedMemorySize, PV_SMEM);

    // 0. pre-split inputs
    split_kernel<<<(MROWS * DD / 4 + 255) / 256, 256>>>(x, xh, xl, MROWS * DD / 4);
    split_kernel<<<(DD * 3 * DD / 4 + 255) / 256, 256>>>(w_in, wih, wil, DD * 3 * DD / 4);
    split_kernel<<<(DD * DD / 4 + 255) / 256, 256>>>(w_out, woh, wol, DD * DD / 4);

    // 1. QKV GEMM -> split q/k/v per head (q,k 2-pass; v 3-pass)
    mma_gemm_qkv<<<dim3(3 * DD / 128, MROWS / 128), 256, GEMM_SMEM>>>(
        xh, xl, wih, wil, b_in, qh, ql, kh, kl, vh, vl, MROWS, 3 * DD, DD);

    // 2. scores + softmax (2-pass MMA) -> split P
    attn_scores_mma<<<dim3(SS / 32, HH, BB), 256, SC2_SMEM>>>(qh, ql, kh, ph, pl);

    // 3. P @ V (3-pass MMA) -> split AO
    attn_pv_mma<<<dim3(SS / 128, HH, BB), 256, PV_SMEM>>>(ph, pl, vh, vl, aoh, aol);

    // 4. head-mean
    attn_mean_kernel<<<(BB * SS * SS / 8) / 256, 256>>>(ph, pl, out + (size_t)BB * SS * SS);

    // 5. output projection (3-pass)
    mma_gemm_out<<<dim3(DD / 128, MROWS / 128), 256, GEMM_SMEM>>>(
        aoh, aol, woh, wol, b_out, out, MROWS, DD, DD);
}

// round 9
// speedup vs baseline: 1.1758x; 1.0109x over previous
#include <cuda_runtime.h>
#include <cuda_bf16.h>
#include <cstdint>

// Problem constants
#define BB 4
#define SS 1024
#define DD 1024
#define HH 16
#define HD 64
#define MROWS (BB*SS)          // 4096
#define QSCALE 0.03125f        // 1024^-0.5

// ---------------------------------------------------------------------------
// Scratch
// ---------------------------------------------------------------------------
__device__ __nv_bfloat16 g_xh[(size_t)MROWS * DD],   g_xl[(size_t)MROWS * DD];
__device__ __nv_bfloat16 g_wih[(size_t)DD * 3 * DD], g_wil[(size_t)DD * 3 * DD];
__device__ __nv_bfloat16 g_woh[(size_t)DD * DD],     g_wol[(size_t)DD * DD];
__device__ __nv_bfloat16 g_qh[(size_t)BB*HH*SS*HD],  g_ql[(size_t)BB*HH*SS*HD];
__device__ __nv_bfloat16 g_kh[(size_t)BB*HH*SS*HD],  g_kl[(size_t)BB*HH*SS*HD];
__device__ __nv_bfloat16 g_vh[(size_t)BB*HH*SS*HD],  g_vl[(size_t)BB*HH*SS*HD];
__device__ __nv_bfloat16 g_ph[(size_t)BB*HH*SS*SS],  g_pl[(size_t)BB*HH*SS*SS];
__device__ __nv_bfloat16 g_aoh[(size_t)MROWS * DD],  g_aol[(size_t)MROWS * DD];

// ---------------------------------------------------------------------------
// MMA / ldmatrix / cp.async helpers
// ---------------------------------------------------------------------------
__device__ __forceinline__ void mma16816(float* d, const uint32_t* a, const uint32_t* b) {
    asm volatile(
        "mma.sync.aligned.m16n8k16.row.col.f32.bf16.bf16.f32 "
        "{%0,%1,%2,%3}, {%4,%5,%6,%7}, {%8,%9}, {%0,%1,%2,%3};"
        : "+f"(d[0]), "+f"(d[1]), "+f"(d[2]), "+f"(d[3])
        : "r"(a[0]), "r"(a[1]), "r"(a[2]), "r"(a[3]), "r"(b[0]), "r"(b[1]));
}
__device__ __forceinline__ void ldsm_x4(uint32_t* r, uint32_t addr) {
    asm volatile("ldmatrix.sync.aligned.m8n8.x4.shared.b16 {%0,%1,%2,%3}, [%4];"
                 : "=r"(r[0]), "=r"(r[1]), "=r"(r[2]), "=r"(r[3]) : "r"(addr));
}
__device__ __forceinline__ void ldsm_x2t(uint32_t* r, uint32_t addr) {
    asm volatile("ldmatrix.sync.aligned.m8n8.x2.trans.shared.b16 {%0,%1}, [%2];"
                 : "=r"(r[0]), "=r"(r[1]) : "r"(addr));
}
__device__ __forceinline__ void split_bf16(float v, __nv_bfloat16& h, __nv_bfloat16& l) {
    h = __float2bfloat16(v);
    l = __float2bfloat16(v - __bfloat162float(h));
}
__device__ __forceinline__ void cpa16(uint32_t s, const void* g) {
    asm volatile("cp.async.cg.shared.global [%0], [%1], 16;" :: "r"(s), "l"(g));
}
__device__ __forceinline__ void cp_commit() { asm volatile("cp.async.commit_group;"); }
template<int N> __device__ __forceinline__ void cp_wait() {
    asm volatile("cp.async.wait_group %0;" :: "n"(N));
}

// ---------------------------------------------------------------------------
// split kernel: fp32 -> (hi, lo) bf16
// ---------------------------------------------------------------------------
__global__ __launch_bounds__(256) void split_kernel(
    const float* __restrict__ in, __nv_bfloat16* __restrict__ hi,
    __nv_bfloat16* __restrict__ lo, int n4)
{
    int i = blockIdx.x * 256 + threadIdx.x;
    if (i >= n4) return;
    float4 v = ((const float4*)in)[i];
    __nv_bfloat16 h0, l0, h1, l1, h2, l2, h3, l3;
    split_bf16(v.x, h0, l0); split_bf16(v.y, h1, l1);
    split_bf16(v.z, h2, l2); split_bf16(v.w, h3, l3);
    ((__nv_bfloat162*)hi)[2 * i]     = __nv_bfloat162(h0, h1);
    ((__nv_bfloat162*)hi)[2 * i + 1] = __nv_bfloat162(h2, h3);
    ((__nv_bfloat162*)lo)[2 * i]     = __nv_bfloat162(l0, l1);
    ((__nv_bfloat162*)lo)[2 * i + 1] = __nv_bfloat162(l2, l3);
}

// ---------------------------------------------------------------------------
// GEMM tile (BM=BN=128, BK=32): 4 warps (128 thr), warp tile 64x64.
// 3-stage cp.async pipeline, one barrier per iter.
// p3expr (per-CTA uniform): 3-pass (use B-lo) vs 2-pass (B-hi only).
// ---------------------------------------------------------------------------
#define ASTR 40
#define BSTR 136
#define AH_OFF 0
#define AL_OFF 10240
#define BH_OFF 20480
#define BL_OFF 29184
#define STAGE_B 37888
#define GEMM_SMEM (STAGE_B * 3)

#define GEMM_PROLOG(p3expr) \
    extern __shared__ char dynsm[]; \
    uint32_t smbase = (uint32_t)__cvta_generic_to_shared(dynsm); \
    int bx = blockIdx.x, by = blockIdx.y; \
    int tid = threadIdx.x, lane = tid & 31, wid = tid >> 5; \
    int wm = (wid & 1) * 64, wn = (wid >> 1) * 64; \
    const bool p3 = (p3expr); \
    uint32_t a_off = (uint32_t)((wm + (lane & 15)) * ASTR + (lane >> 4) * 8) * 2; \
    uint32_t b_off = (uint32_t)((lane & 15) * BSTR + wn) * 2; \
    float acc[4][8][4]; \
    _Pragma("unroll") for (int i = 0; i < 4; i++) \
        _Pragma("unroll") for (int j = 0; j < 8; j++) \
            _Pragma("unroll") for (int c = 0; c < 4; c++) acc[i][j][c] = 0.f; \
    const int nk = K >> 5; \
    auto load_stage = [&](int st, int kt) { \
        uint32_t sb = smbase + st * STAGE_B; \
        _Pragma("unroll") for (int i = 0; i < 4; i++) { \
            int row = (tid >> 2) + i * 32; \
            size_t g = (size_t)(by * 128 + row) * K + kt + (tid & 3) * 8; \
            cpa16(sb + AH_OFF + (uint32_t)(row * ASTR + (tid & 3) * 8) * 2, Ahg + g); \
            cpa16(sb + AL_OFF + (uint32_t)(row * ASTR + (tid & 3) * 8) * 2, Alg + g); \
        } \
        _Pragma("unroll") for (int i = 0; i < 4; i++) { \
            int row = (tid >> 4) + i * 8; \
            size_t g = (size_t)(kt + row) * N + bx * 128 + (tid & 15) * 8; \
            cpa16(sb + BH_OFF + (uint32_t)(row * BSTR + (tid & 15) * 8) * 2, Bhg + g); \
            if (p3) cpa16(sb + BL_OFF + (uint32_t)(row * BSTR + (tid & 15) * 8) * 2, Blg + g); \
        } \
        cp_commit(); \
    }; \
    load_stage(0, 0); \
    load_stage(1, 32); \
    for (int i = 0; i < nk; i++) { \
        if (i + 1 < nk) cp_wait<1>(); else cp_wait<0>(); \
        __syncthreads(); \
        if (i + 2 < nk) load_stage((i + 2) % 3, (i + 2) * 32); \
        uint32_t sb = smbase + (i % 3) * STAGE_B; \
        _Pragma("unroll") for (int ks = 0; ks < 2; ks++) { \
            uint32_t ahf[4][4], alf[4][4]; \
            _Pragma("unroll") for (int mi = 0; mi < 4; mi++) { \
                uint32_t off = a_off + (uint32_t)(mi * 16 * ASTR + ks * 16) * 2; \
                ldsm_x4(ahf[mi], sb + AH_OFF + off); \
                ldsm_x4(alf[mi], sb + AL_OFF + off); \
            } \
            _Pragma("unroll") for (int nb = 0; nb < 2; nb++) { \
                uint32_t bhf[4][2]; \
                _Pragma("unroll") for (int nj = 0; nj < 4; nj++) { \
                    uint32_t off = b_off + (uint32_t)(ks * 16 * BSTR + (nb * 4 + nj) * 8) * 2; \
                    ldsm_x2t(bhf[nj], sb + BH_OFF + off); \
                } \
                _Pragma("unroll") for (int nj = 0; nj < 4; nj++) \
                    _Pragma("unroll") for (int mi = 0; mi < 4; mi++) \
                        mma16816(acc[mi][nb * 4 + nj], ahf[mi], bhf[nj]); \
                _Pragma("unroll") for (int nj = 0; nj < 4; nj++) \
                    _Pragma("unroll") for (int mi = 0; mi < 4; mi++) \
                        mma16816(acc[mi][nb * 4 + nj], alf[mi], bhf[nj]); \
                if (p3) { \
                    uint32_t blf[4][2]; \
                    _Pragma("unroll") for (int nj = 0; nj < 4; nj++) { \
                        uint32_t off = b_off + (uint32_t)(ks * 16 * BSTR + (nb * 4 + nj) * 8) * 2; \
                        ldsm_x2t(blf[nj], sb + BL_OFF + off); \
                    } \
                    _Pragma("unroll") for (int nj = 0; nj < 4; nj++) \
                        _Pragma("unroll") for (int mi = 0; mi < 4; mi++) \
                            mma16816(acc[mi][nb * 4 + nj], ahf[mi], blf[nj]); \
                } \
            } \
        } \
    } \
    __syncthreads();

// ---------------------------------------------------------------------------
// QKV GEMM: writes q (scaled), k, v as split bf16 in [b,h,s,d] layout
// q,k thirds: 2-pass (B-lo dropped); v third: 3-pass (feeds output directly)
// ---------------------------------------------------------------------------
__global__ __launch_bounds__(128, 2) void mma_gemm_qkv(
    const __nv_bfloat16* __restrict__ Ahg, const __nv_bfloat16* __restrict__ Alg,
    const __nv_bfloat16* __restrict__ Bhg, const __nv_bfloat16* __restrict__ Blg,
    const float* __restrict__ bias,
    __nv_bfloat16* __restrict__ qh, __nv_bfloat16* __restrict__ ql,
    __nv_bfloat16* __restrict__ kh, __nv_bfloat16* __restrict__ kl,
    __nv_bfloat16* __restrict__ vh, __nv_bfloat16* __restrict__ vl,
    int M, int N, int K)
{
    GEMM_PROLOG(blockIdx.x >= 16)   // v part (cols >= 2048) gets 3 passes

    int part = (bx * 128) >> 10;
    __nv_bfloat16* dh = part == 0 ? qh : (part == 1 ? kh : vh);
    __nv_bfloat16* dl = part == 0 ? ql : (part == 1 ? kl : vl);
    float mul = part == 0 ? QSCALE : 1.0f;
    int head = ((bx * 128 + wn) & 1023) >> 6;
    int bq = (by * 128) >> 10;
    int group = lane >> 2, tig = lane & 3;
    #pragma unroll
    for (int mi = 0; mi < 4; mi++) {
        int s0 = ((by * 128) & 1023) + wm + mi * 16 + group;
        #pragma unroll
        for (int ni = 0; ni < 8; ni++) {
            int col = bx * 128 + wn + ni * 8 + tig * 2;
            int d = ni * 8 + tig * 2;
            float b0 = bias[col], b1 = bias[col + 1];
            float v00 = (acc[mi][ni][0] + b0) * mul, v01 = (acc[mi][ni][1] + b1) * mul;
            float v10 = (acc[mi][ni][2] + b0) * mul, v11 = (acc[mi][ni][3] + b1) * mul;
            size_t o0 = ((size_t)(bq * HH + head) * SS + s0) * HD + d;
            size_t o1 = o0 + 8 * HD;
            __nv_bfloat16 h0, l0, h1, l1;
            split_bf16(v00, h0, l0); split_bf16(v01, h1, l1);
            *(__nv_bfloat162*)&dh[o0] = __nv_bfloat162(h0, h1);
            *(__nv_bfloat162*)&dl[o0] = __nv_bfloat162(l0, l1);
            split_bf16(v10, h0, l0); split_bf16(v11, h1, l1);
            *(__nv_bfloat162*)&dh[o1] = __nv_bfloat162(h0, h1);
            *(__nv_bfloat162*)&dl[o1] = __nv_bfloat162(l0, l1);
        }
    }
}

// ---------------------------------------------------------------------------
// Out-projection GEMM: fp32 output + bias, full 3-pass
// ---------------------------------------------------------------------------
__global__ __launch_bounds__(128, 2) void mma_gemm_out(
    const __nv_bfloat16* __restrict__ Ahg, const __nv_bfloat16* __restrict__ Alg,
    const __nv_bfloat16* __restrict__ Bhg, const __nv_bfloat16* __restrict__ Blg,
    const float* __restrict__ bias, float* __restrict__ C,
    int M, int N, int K)
{
    GEMM_PROLOG(true)

    int group = lane >> 2, tig = lane & 3;
    #pragma unroll
    for (int mi = 0; mi < 4; mi++) {
        int row0 = by * 128 + wm + mi * 16 + group;
        #pragma unroll
        for (int ni = 0; ni < 8; ni++) {
            int col = bx * 128 + wn + ni * 8 + tig * 2;
            float b0 = bias[col], b1 = bias[col + 1];
            *(float2*)&C[(size_t)row0 * N + col] =
                make_float2(acc[mi][ni][0] + b0, acc[mi][ni][1] + b1);
            *(float2*)&C[(size_t)(row0 + 8) * N + col] =
                make_float2(acc[mi][ni][2] + b0, acc[mi][ni][3] + b1);
        }
    }
}

// ---------------------------------------------------------------------------
// Scores + softmax (MMA): per (b,h,32q). 2-pass: S = qh*kh + ql*kh.
// K-lo never loaded. smem: Ssc fp32[32][1032] | Qh/Ql [32][72] | Kh x2 stages
// ---------------------------------------------------------------------------
#define SC2_QH 132096
#define SC2_QL 136704
#define SC2_K  141312
#define SC2_KSTAGE 18432
#define SC2_SMEM 178176

__global__ __launch_bounds__(256) void attn_scores_mma(
    const __nv_bfloat16* __restrict__ qh, const __nv_bfloat16* __restrict__ ql,
    const __nv_bfloat16* __restrict__ kh,
    __nv_bfloat16* __restrict__ Ph, __nv_bfloat16* __restrict__ Pl)
{
    extern __shared__ char dynsm[];
    float* Ssc = (float*)dynsm;
    uint32_t smbase = (uint32_t)__cvta_generic_to_shared(dynsm);

    int b = blockIdx.z, h = blockIdx.y, q0 = blockIdx.x * 32;
    int tid = threadIdx.x, lane = tid & 31, wid = tid >> 5;
    int wm = (wid & 1) * 16;
    int wn = (wid >> 1) * 32;

    {
        size_t qb = ((size_t)(b * HH + h) * SS + q0) * HD;
        int row = tid >> 3, c8 = (tid & 7) * 8;
        *(uint4*)(dynsm + SC2_QH + (row * 72 + c8) * 2) = *(const uint4*)&qh[qb + row * 64 + c8];
        *(uint4*)(dynsm + SC2_QL + (row * 72 + c8) * 2) = *(const uint4*)&ql[qb + row * 64 + c8];
    }

    auto load_k = [&](int st, int kt) {
        uint32_t kb = smbase + SC2_K + st * SC2_KSTAGE;
        size_t gb = ((size_t)(b * HH + h) * SS + kt) * HD;
        #pragma unroll
        for (int it = 0; it < 4; it++) {
            int idx = tid + it * 256;
            int row = idx >> 3, c8 = (idx & 7) * 8;
            cpa16(kb + (uint32_t)(row * 72 + c8) * 2, kh + gb + row * 64 + c8);
        }
        cp_commit();
    };
    load_k(0, 0);
    load_k(1, 128);

    uint32_t aq_off = (uint32_t)((wm + (lane & 15)) * 72 + (lane >> 4) * 8) * 2;
    int rr_ = lane & 7, halfk = (lane >> 3) & 1, q2 = lane >> 4;
    uint32_t bk_off = (uint32_t)((wn + q2 * 8 + rr_) * 72 + halfk * 8) * 2;

    for (int i = 0; i < 8; i++) {
        if (i < 7) cp_wait<1>(); else cp_wait<0>();
        __syncthreads();
        uint32_t kb = smbase + SC2_K + (i & 1) * SC2_KSTAGE;

        float acc[4][4];
        #pragma unroll
        for (int a = 0; a < 4; a++)
            #pragma unroll
            for (int c = 0; c < 4; c++) acc[a][c] = 0.f;

        #pragma unroll
        for (int ks = 0; ks < 4; ks++) {
            uint32_t ahf[4], alf[4];
            ldsm_x4(ahf, smbase + SC2_QH + aq_off + ks * 32);
            ldsm_x4(alf, smbase + SC2_QL + aq_off + ks * 32);
            uint32_t bhf[2][4];
            #pragma unroll
            for (int ni2 = 0; ni2 < 2; ni2++) {
                uint32_t boff = bk_off + (uint32_t)(ni2 * 16 * 72 + ks * 16) * 2;
                ldsm_x4(bhf[ni2], kb + boff);
            }
            #pragma unroll
            for (int ni2 = 0; ni2 < 2; ni2++) {
                mma16816(acc[ni2*2],   ahf, bhf[ni2]);
                mma16816(acc[ni2*2+1], ahf, bhf[ni2] + 2);
            }
            #pragma unroll
            for (int ni2 = 0; ni2 < 2; ni2++) {
                mma16816(acc[ni2*2],   alf, bhf[ni2]);
                mma16816(acc[ni2*2+1], alf, bhf[ni2] + 2);
            }
        }

        int kt = i * 128;
        int group = lane >> 2, tig = lane & 3;
        #pragma unroll
        for (int ni = 0; ni < 4; ni++) {
            int row = wm + group;
            int col = kt + wn + ni * 8 + tig * 2;
            *(float2*)&Ssc[row * 1032 + col]       = make_float2(acc[ni][0], acc[ni][1]);
            *(float2*)&Ssc[(row + 8) * 1032 + col] = make_float2(acc[ni][2], acc[ni][3]);
        }
        __syncthreads();
        if (i + 2 < 8) load_k((i + 2) & 1, (i + 2) * 128);
    }

    for (int rr = 0; rr < 4; rr++) {
        int row = wid * 4 + rr;
        float2 v2[16];
        float m = -1e30f;
        #pragma unroll
        for (int i2 = 0; i2 < 16; i2++) {
            v2[i2] = *(float2*)&Ssc[row * 1032 + (lane + i2 * 32) * 2];
            m = fmaxf(m, fmaxf(v2[i2].x, v2[i2].y));
        }
        #pragma unroll
        for (int o = 16; o; o >>= 1) m = fmaxf(m, __shfl_xor_sync(0xffffffffu, m, o));
        float s = 0.f;
        #pragma unroll
        for (int i2 = 0; i2 < 16; i2++) {
            v2[i2].x = __expf(v2[i2].x - m);
            v2[i2].y = __expf(v2[i2].y - m);
            s += v2[i2].x + v2[i2].y;
        }
        #pragma unroll
        for (int o = 16; o; o >>= 1) s += __shfl_xor_sync(0xffffffffu, s, o);
        float inv = 1.f / s;
        size_t gb = ((size_t)(b * HH + h) * SS + q0 + row) * SS;
        #pragma unroll
        for (int i2 = 0; i2 < 16; i2++) {
            float p0 = v2[i2].x * inv, p1 = v2[i2].y * inv;
            __nv_bfloat16 h0, l0, h1, l1;
            split_bf16(p0, h0, l0); split_bf16(p1, h1, l1);
            size_t o = gb + (size_t)(lane + i2 * 32) * 2;
            *(__nv_bfloat162*)&Ph[o] = __nv_bfloat162(h0, h1);
            *(__nv_bfloat162*)&Pl[o] = __nv_bfloat162(l0, l1);
        }
    }
}

// ---------------------------------------------------------------------------
// PV (MMA): AO = P @ V per (b,h,256q). 8 warps x (32q x 64d) warp tiles.
// Full 3-pass (accuracy-critical). 2-stage cp.async.
// ---------------------------------------------------------------------------
#define PV_PH 0
#define PV_PL 36864
#define PV_VH 73728
#define PV_VL 82944
#define PV_STAGE 92160
#define PV_SMEM 184320

__global__ __launch_bounds__(256) void attn_pv_mma(
    const __nv_bfloat16* __restrict__ Ph, const __nv_bfloat16* __restrict__ Pl,
    const __nv_bfloat16* __restrict__ vh, const __nv_bfloat16* __restrict__ vl,
    __nv_bfloat16* __restrict__ AOh, __nv_bfloat16* __restrict__ AOl)
{
    extern __shared__ char dynsm[];
    uint32_t smbase = (uint32_t)__cvta_generic_to_shared(dynsm);

    int b = blockIdx.z, h = blockIdx.y, q0 = blockIdx.x * 256;
    int tid = threadIdx.x, lane = tid & 31, wid = tid >> 5;

    auto load_stage = [&](int st, int kt) {
        uint32_t sb = smbase + st * PV_STAGE;
        size_t pb = ((size_t)(b * HH + h) * SS + q0) * SS + kt;
        #pragma unroll
        for (int it = 0; it < 8; it++) {
            int idx = tid + it * 256;
            int row = idx >> 3, c8 = (idx & 7) * 8;
            cpa16(sb + PV_PH + (uint32_t)(row * 72 + c8) * 2, Ph + pb + (size_t)row * SS + c8);
            cpa16(sb + PV_PL + (uint32_t)(row * 72 + c8) * 2, Pl + pb + (size_t)row * SS + c8);
        }
        size_t vb = ((size_t)(b * HH + h) * SS + kt) * HD;
        #pragma unroll
        for (int it = 0; it < 2; it++) {
            int idx = tid + it * 256;
            int row = idx >> 3, c8 = (idx & 7) * 8;
            cpa16(sb + PV_VH + (uint32_t)(row * 72 + c8) * 2, vh + vb + row * 64 + c8);
            cpa16(sb + PV_VL + (uint32_t)(row * 72 + c8) * 2, vl + vb + row * 64 + c8);
        }
        cp_commit();
    };

    float acc[2][8][4];
    #pragma unroll
    for (int a = 0; a < 2; a++)
        #pragma unroll
        for (int j = 0; j < 8; j++)
            #pragma unroll
            for (int c = 0; c < 4; c++) acc[a][j][c] = 0.f;

    uint32_t ap_off = (uint32_t)((wid * 32 + (lane & 15)) * 72 + (lane >> 4) * 8) * 2;
    uint32_t bv_off = (uint32_t)((lane & 15) * 72) * 2;

    load_stage(0, 0);
    load_stage(1, 64);

    for (int i = 0; i < 16; i++) {
        if (i < 15) cp_wait<1>(); else cp_wait<0>();
        __syncthreads();
        uint32_t sb = smbase + (i & 1) * PV_STAGE;
        #pragma unroll
        for (int ks = 0; ks < 4; ks++) {
            uint32_t ahf[2][4], alf[2][4];
            #pragma unroll
            for (int mi = 0; mi < 2; mi++) {
                uint32_t off = ap_off + (uint32_t)(mi * 16 * 72 + ks * 16) * 2;
                ldsm_x4(ahf[mi], sb + PV_PH + off);
                ldsm_x4(alf[mi], sb + PV_PL + off);
            }
            #pragma unroll
            for (int nb = 0; nb < 2; nb++) {
                uint32_t bhf[4][2], blf[4][2];
                #pragma unroll
                for (int nj = 0; nj < 4; nj++) {
                    uint32_t off = bv_off + (uint32_t)(ks * 16 * 72 + (nb * 4 + nj) * 8) * 2;
                    ldsm_x2t(bhf[nj], sb + PV_VH + off);
                    ldsm_x2t(blf[nj], sb + PV_VL + off);
                }
                #pragma unroll
                for (int nj = 0; nj < 4; nj++)
                    #pragma unroll
                    for (int mi = 0; mi < 2; mi++)
                        mma16816(acc[mi][nb*4+nj], ahf[mi], bhf[nj]);
                #pragma unroll
                for (int nj = 0; nj < 4; nj++)
                    #pragma unroll
                    for (int mi = 0; mi < 2; mi++)
                        mma16816(acc[mi][nb*4+nj], ahf[mi], blf[nj]);
                #pragma unroll
                for (int nj = 0; nj < 4; nj++)
                    #pragma unroll
                    for (int mi = 0; mi < 2; mi++)
                        mma16816(acc[mi][nb*4+nj], alf[mi], bhf[nj]);
            }
        }
        __syncthreads();
        if (i + 2 < 16) load_stage((i + 2) & 1, (i + 2) * 64);
    }

    int group = lane >> 2, tig = lane & 3;
    #pragma unroll
    for (int mi = 0; mi < 2; mi++) {
        #pragma unroll
        for (int ni = 0; ni < 8; ni++) {
            int d = ni * 8 + tig * 2;
            int r0 = q0 + wid * 32 + mi * 16 + group;
            size_t o0 = (size_t)(b * SS + r0) * DD + h * HD + d;
            size_t o1 = o0 + (size_t)8 * DD;
            __nv_bfloat16 h0, l0, h1, l1;
            split_bf16(acc[mi][ni][0], h0, l0); split_bf16(acc[mi][ni][1], h1, l1);
            *(__nv_bfloat162*)&AOh[o0] = __nv_bfloat162(h0, h1);
            *(__nv_bfloat162*)&AOl[o0] = __nv_bfloat162(l0, l1);
            split_bf16(acc[mi][ni][2], h0, l0); split_bf16(acc[mi][ni][3], h1, l1);
            *(__nv_bfloat162*)&AOh[o1] = __nv_bfloat162(h0, h1);
            *(__nv_bfloat162*)&AOl[o1] = __nv_bfloat162(l0, l1);
        }
    }
}

// ---------------------------------------------------------------------------
// attn_mean[b,q,k] = (1/H) * sum_h (Ph + Pl)
// ---------------------------------------------------------------------------
__global__ __launch_bounds__(256) void attn_mean_kernel(
    const __nv_bfloat16* __restrict__ Ph, const __nv_bfloat16* __restrict__ Pl,
    float* __restrict__ outm)
{
    size_t g = (size_t)blockIdx.x * 256 + threadIdx.x;
    int k8 = (int)(g & 127);
    size_t t = g >> 7;
    int q = (int)(t & 1023);
    int b = (int)(t >> 10);
    size_t k = (size_t)k8 * 8;

    float acc8[8];
    #pragma unroll
    for (int j = 0; j < 8; j++) acc8[j] = 0.f;
    #pragma unroll
    for (int h = 0; h < HH; h++) {
        size_t off = ((size_t)(b * HH + h) * SS + q) * SS + k;
        uint4 vh4 = *(const uint4*)&Ph[off];
        uint4 vl4 = *(const uint4*)&Pl[off];
        const uint32_t* ph = (const uint32_t*)&vh4;
        const uint32_t* pl = (const uint32_t*)&vl4;
        #pragma unroll
        for (int j = 0; j < 4; j++) {
            __nv_bfloat162 hh = *(__nv_bfloat162*)&ph[j];
            __nv_bfloat162 ll = *(__nv_bfloat162*)&pl[j];
            acc8[2*j]   += __low2float(hh)  + __low2float(ll);
            acc8[2*j+1] += __high2float(hh) + __high2float(ll);
        }
    }
    size_t ob = ((size_t)(b * SS + q)) * SS + k;
    const float inv = 1.0f / HH;
    float4 o0 = make_float4(acc8[0]*inv, acc8[1]*inv, acc8[2]*inv, acc8[3]*inv);
    float4 o1 = make_float4(acc8[4]*inv, acc8[5]*inv, acc8[6]*inv, acc8[7]*inv);
    *(float4*)&outm[ob]     = o0;
    *(float4*)&outm[ob + 4] = o1;
}

// ---------------------------------------------------------------------------
// Host launcher
// ---------------------------------------------------------------------------
extern "C" void kernel_launch(void* const* d_in, const int* in_sizes, int n_in,
                              void* d_out, int out_size)
{
    const float* x     = (const float*)d_in[0];
    const float* w_in  = (const float*)d_in[1];
    const float* b_in  = (const float*)d_in[2];
    const float* w_out = (const float*)d_in[3];
    const float* b_out = (const float*)d_in[4];
    float* out = (float*)d_out;

    __nv_bfloat16 *xh, *xl, *wih, *wil, *woh, *wol;
    __nv_bfloat16 *qh, *ql, *kh, *kl, *vh, *vl, *ph, *pl, *aoh, *aol;
    cudaGetSymbolAddress((void**)&xh,  g_xh);
    cudaGetSymbolAddress((void**)&xl,  g_xl);
    cudaGetSymbolAddress((void**)&wih, g_wih);
    cudaGetSymbolAddress((void**)&wil, g_wil);
    cudaGetSymbolAddress((void**)&woh, g_woh);
    cudaGetSymbolAddress((void**)&wol, g_wol);
    cudaGetSymbolAddress((void**)&qh,  g_qh);
    cudaGetSymbolAddress((void**)&ql,  g_ql);
    cudaGetSymbolAddress((void**)&kh,  g_kh);
    cudaGetSymbolAddress((void**)&kl,  g_kl);
    cudaGetSymbolAddress((void**)&vh,  g_vh);
    cudaGetSymbolAddress((void**)&vl,  g_vl);
    cudaGetSymbolAddress((void**)&ph,  g_ph);
    cudaGetSymbolAddress((void**)&pl,  g_pl);
    cudaGetSymbolAddress((void**)&aoh, g_aoh);
    cudaGetSymbolAddress((void**)&aol, g_aol);

    cudaFuncSetAttribute(mma_gemm_qkv,
                         cudaFuncAttributeMaxDynamicSharedMemorySize, GEMM_SMEM);
    cudaFuncSetAttribute(mma_gemm_out,
                         cudaFuncAttributeMaxDynamicSharedMemorySize, GEMM_SMEM);
    cudaFuncSetAttribute(attn_scores_mma,
                         cudaFuncAttributeMaxDynamicSharedMemorySize, SC2_SMEM);
    cudaFuncSetAttribute(attn_pv_mma,
                         cudaFuncAttributeMaxDynamicSharedMemorySize, PV_SMEM);

    // 0. pre-split inputs
    split_kernel<<<(MROWS * DD / 4 + 255) / 256, 256>>>(x, xh, xl, MROWS * DD / 4);
    split_kernel<<<(DD * 3 * DD / 4 + 255) / 256, 256>>>(w_in, wih, wil, DD * 3 * DD / 4);
    split_kernel<<<(DD * DD / 4 + 255) / 256, 256>>>(w_out, woh, wol, DD * DD / 4);

    // 1. QKV GEMM -> split q/k/v per head (q,k 2-pass; v 3-pass)
    mma_gemm_qkv<<<dim3(3 * DD / 128, MROWS / 128), 128, GEMM_SMEM>>>(
        xh, xl, wih, wil, b_in, qh, ql, kh, kl, vh, vl, MROWS, 3 * DD, DD);

    // 2. scores + softmax (2-pass MMA) -> split P
    attn_scores_mma<<<dim3(SS / 32, HH, BB), 256, SC2_SMEM>>>(qh, ql, kh, ph, pl);

    // 3. P @ V (3-pass MMA, 256q CTAs) -> split AO
    attn_pv_mma<<<dim3(SS / 256, HH, BB), 256, PV_SMEM>>>(ph, pl, vh, vl, aoh, aol);

    // 4. head-mean
    attn_mean_kernel<<<(BB * SS * SS / 8) / 256, 256>>>(ph, pl, out + (size_t)BB * SS * SS);

    // 5. output projection (3-pass)
    mma_gemm_out<<<dim3(DD / 128, MROWS / 128), 128, GEMM_SMEM>>>(
        aoh, aol, woh, wol, b_out, out, MROWS, DD, DD);
}